// round 1
// baseline (speedup 1.0000x reference)
#include <cuda_runtime.h>
#include <cuda_bf16.h>
#include <cstdint>

// Problem constants
#define B_   16
#define NP_  4096
#define NT_  77
#define QD_  512
#define CD_  768
#define H_   8
#define DH_  64
#define INNER_ 512   // H*DH

// ---------------------------------------------------------------------------
// Scratch (device globals; allocation inside kernel_launch is forbidden)
// ---------------------------------------------------------------------------
__device__ float g_Q[(size_t)B_ * NP_ * INNER_];   // 134 MB
__device__ float g_Kp[(size_t)B_ * NT_ * INNER_];  // 2.5 MB
__device__ float g_Vp[(size_t)B_ * NT_ * INNER_];  // 2.5 MB
__device__ float g_Att[(size_t)B_ * NP_ * INNER_]; // 134 MB

// ---------------------------------------------------------------------------
// SGEMM: C[M,N] = A[M,K] @ B[K,N] (+bias). Row-major everything.
// 128x128 block tile, BK=8, 8x8 per thread, 256 threads, reg-staged prefetch.
// Requires: N % 128 == 0, K % 8 == 0. M arbitrary (guarded).
// ---------------------------------------------------------------------------
template<bool HAS_BIAS>
__global__ __launch_bounds__(256, 2)
void sgemm_kernel(const float* __restrict__ A, const float* __restrict__ Bm,
                  const float* __restrict__ bias, float* __restrict__ C,
                  int M, int N, int K)
{
    __shared__ float As[8][128];
    __shared__ float Bs[8][128];

    const int tid = threadIdx.x;
    const int m0 = blockIdx.y * 128;
    const int n0 = blockIdx.x * 128;

    // A tile load mapping: 128 rows x 8 cols, float4 per thread
    const int arow = tid >> 1;           // 0..127
    const int acol = (tid & 1) * 4;      // 0 or 4
    // B tile load mapping: 8 rows x 128 cols, float4 per thread
    const int brow = tid >> 5;           // 0..7
    const int bcol = (tid & 31) * 4;     // 0..124

    const int tx = tid & 15;             // C col group
    const int ty = tid >> 4;             // C row group

    float acc[8][8];
    #pragma unroll
    for (int i = 0; i < 8; i++)
        #pragma unroll
        for (int j = 0; j < 8; j++) acc[i][j] = 0.f;

    float4 ta, tb;

    // prologue: tile 0
    if (m0 + arow < M)
        ta = *reinterpret_cast<const float4*>(A + (size_t)(m0 + arow) * K + acol);
    else
        ta = make_float4(0.f, 0.f, 0.f, 0.f);
    tb = *reinterpret_cast<const float4*>(Bm + (size_t)brow * N + n0 + bcol);
    As[acol + 0][arow] = ta.x; As[acol + 1][arow] = ta.y;
    As[acol + 2][arow] = ta.z; As[acol + 3][arow] = ta.w;
    *reinterpret_cast<float4*>(&Bs[brow][bcol]) = tb;
    __syncthreads();

    const int ntiles = K >> 3;
    for (int t = 0; t < ntiles; t++) {
        const int knext = (t + 1) << 3;
        if (t + 1 < ntiles) {
            if (m0 + arow < M)
                ta = *reinterpret_cast<const float4*>(A + (size_t)(m0 + arow) * K + knext + acol);
            else
                ta = make_float4(0.f, 0.f, 0.f, 0.f);
            tb = *reinterpret_cast<const float4*>(Bm + (size_t)(knext + brow) * N + n0 + bcol);
        }

        #pragma unroll
        for (int k = 0; k < 8; k++) {
            float ra[8], rb[8];
            *reinterpret_cast<float4*>(&ra[0]) = *reinterpret_cast<const float4*>(&As[k][ty * 8]);
            *reinterpret_cast<float4*>(&ra[4]) = *reinterpret_cast<const float4*>(&As[k][ty * 8 + 4]);
            *reinterpret_cast<float4*>(&rb[0]) = *reinterpret_cast<const float4*>(&Bs[k][tx * 8]);
            *reinterpret_cast<float4*>(&rb[4]) = *reinterpret_cast<const float4*>(&Bs[k][tx * 8 + 4]);
            #pragma unroll
            for (int i = 0; i < 8; i++)
                #pragma unroll
                for (int j = 0; j < 8; j++)
                    acc[i][j] += ra[i] * rb[j];
        }
        __syncthreads();
        if (t + 1 < ntiles) {
            As[acol + 0][arow] = ta.x; As[acol + 1][arow] = ta.y;
            As[acol + 2][arow] = ta.z; As[acol + 3][arow] = ta.w;
            *reinterpret_cast<float4*>(&Bs[brow][bcol]) = tb;
        }
        __syncthreads();
    }

    // epilogue
    #pragma unroll
    for (int i = 0; i < 8; i++) {
        const int row = m0 + ty * 8 + i;
        if (row < M) {
            float* cp = C + (size_t)row * N + n0 + tx * 8;
            #pragma unroll
            for (int j = 0; j < 8; j += 4) {
                float4 v;
                v.x = acc[i][j + 0]; v.y = acc[i][j + 1];
                v.z = acc[i][j + 2]; v.w = acc[i][j + 3];
                if (HAS_BIAS) {
                    const float* bp = bias + n0 + tx * 8 + j;
                    v.x += bp[0]; v.y += bp[1]; v.z += bp[2]; v.w += bp[3];
                }
                *reinterpret_cast<float4*>(cp + j) = v;
            }
        }
    }
}

// ---------------------------------------------------------------------------
// Fused attention: one thread per (b, h, q-row). K/V tile for (b,h) in smem.
// Unnormalized-exp softmax (scores are O(1); no overflow possible), mask honored.
// ---------------------------------------------------------------------------
__global__ __launch_bounds__(256, 1)
void attn_kernel(const float* __restrict__ Q, const float* __restrict__ Kb,
                 const float* __restrict__ Vb, const int* __restrict__ mask,
                 float* __restrict__ Ob)
{
    __shared__ float Ks[NT_][DH_];
    __shared__ float Vs[NT_][DH_];

    const int b = blockIdx.z;
    const int h = blockIdx.y;
    const int tid = threadIdx.x;
    const int qr = blockIdx.x * 256 + tid;

    // cooperative K/V tile load (coalesced within each 64-wide segment)
    for (int i = tid; i < NT_ * DH_; i += 256) {
        const int j = i >> 6;
        const int d = i & 63;
        const size_t src = ((size_t)(b * NT_ + j)) * INNER_ + h * DH_ + d;
        Ks[j][d] = Kb[src];
        Vs[j][d] = Vb[src];
    }
    __syncthreads();

    // q row into registers
    float q[DH_];
    const float4* qp = reinterpret_cast<const float4*>(
        Q + ((size_t)(b * NP_ + qr)) * INNER_ + h * DH_);
    #pragma unroll
    for (int i = 0; i < 16; i++) {
        float4 v = qp[i];
        q[4 * i + 0] = v.x; q[4 * i + 1] = v.y;
        q[4 * i + 2] = v.z; q[4 * i + 3] = v.w;
    }

    const int* mrow = mask + ((size_t)(b * NP_ + qr)) * NT_;

    float acc[DH_];
    #pragma unroll
    for (int d = 0; d < DH_; d++) acc[d] = 0.f;
    float l = 0.f;

    #pragma unroll 1
    for (int j = 0; j < NT_; j++) {
        const float4* kj = reinterpret_cast<const float4*>(&Ks[j][0]);
        float s0 = 0.f, s1 = 0.f, s2 = 0.f, s3 = 0.f;
        #pragma unroll
        for (int d4 = 0; d4 < 16; d4++) {
            float4 kv = kj[d4];
            s0 += q[4 * d4 + 0] * kv.x;
            s1 += q[4 * d4 + 1] * kv.y;
            s2 += q[4 * d4 + 2] * kv.z;
            s3 += q[4 * d4 + 3] * kv.w;
        }
        const float s = ((s0 + s1) + (s2 + s3)) * 0.125f;  // 1/sqrt(64)
        const float e = (mrow[j] != 0) ? __expf(s) : 0.f;
        l += e;
        const float4* vj = reinterpret_cast<const float4*>(&Vs[j][0]);
        #pragma unroll
        for (int d4 = 0; d4 < 16; d4++) {
            float4 vv = vj[d4];
            acc[4 * d4 + 0] += e * vv.x;
            acc[4 * d4 + 1] += e * vv.y;
            acc[4 * d4 + 2] += e * vv.z;
            acc[4 * d4 + 3] += e * vv.w;
        }
    }

    const float inv = 1.f / l;
    float4* op = reinterpret_cast<float4*>(
        Ob + ((size_t)(b * NP_ + qr)) * INNER_ + h * DH_);
    #pragma unroll
    for (int i = 0; i < 16; i++) {
        float4 v;
        v.x = acc[4 * i + 0] * inv; v.y = acc[4 * i + 1] * inv;
        v.z = acc[4 * i + 2] * inv; v.w = acc[4 * i + 3] * inv;
        op[i] = v;
    }
}

// ---------------------------------------------------------------------------
// Launch: Qproj -> K/Vproj -> attention -> Oproj(+bias)
// Inputs: x, context, mask, Wq, Wk, Wv, Wo, bo
// ---------------------------------------------------------------------------
extern "C" void kernel_launch(void* const* d_in, const int* in_sizes, int n_in,
                              void* d_out, int out_size)
{
    const float* x    = (const float*)d_in[0];
    const float* ctx  = (const float*)d_in[1];
    const int*   mask = (const int*)  d_in[2];
    const float* Wq   = (const float*)d_in[3];
    const float* Wk   = (const float*)d_in[4];
    const float* Wv   = (const float*)d_in[5];
    const float* Wo   = (const float*)d_in[6];
    const float* bo   = (const float*)d_in[7];
    float* out = (float*)d_out;

    float *Qb, *Kb, *Vb, *Ab;
    cudaGetSymbolAddress((void**)&Qb, g_Q);
    cudaGetSymbolAddress((void**)&Kb, g_Kp);
    cudaGetSymbolAddress((void**)&Vb, g_Vp);
    cudaGetSymbolAddress((void**)&Ab, g_Att);

    const int Mq = B_ * NP_;   // 65536
    const int Mc = B_ * NT_;   // 1232

    // Q = x @ Wq : [65536,512] = [65536,512] @ [512,512]
    sgemm_kernel<false><<<dim3(INNER_ / 128, Mq / 128), 256>>>(
        x, Wq, nullptr, Qb, Mq, INNER_, QD_);

    // K = ctx @ Wk, V = ctx @ Wv : [1232,512] = [1232,768] @ [768,512]
    sgemm_kernel<false><<<dim3(INNER_ / 128, (Mc + 127) / 128), 256>>>(
        ctx, Wk, nullptr, Kb, Mc, INNER_, CD_);
    sgemm_kernel<false><<<dim3(INNER_ / 128, (Mc + 127) / 128), 256>>>(
        ctx, Wv, nullptr, Vb, Mc, INNER_, CD_);

    // fused attention
    attn_kernel<<<dim3(NP_ / 256, H_, B_), 256>>>(Qb, Kb, Vb, mask, Ab);

    // out = Att @ Wo + bo
    sgemm_kernel<true><<<dim3(QD_ / 128, Mq / 128), 256>>>(
        Ab, Wo, bo, out, Mq, QD_, INNER_);
}

// round 3
// speedup vs baseline: 1.4632x; 1.4632x over previous
#include <cuda_runtime.h>
#include <cuda_bf16.h>
#include <cstdint>

// Problem constants
#define B_   16
#define NP_  4096
#define NT_  77
#define QD_  512
#define CD_  768
#define H_   8
#define DH_  64
#define INNER_ 512   // H*DH

// ---------------------------------------------------------------------------
// Scratch (device globals)
// ---------------------------------------------------------------------------
__device__ float          g_Q  [(size_t)B_ * NP_ * INNER_];
__device__ float          g_Kp [(size_t)B_ * NT_ * INNER_];
__device__ float          g_Vp [(size_t)B_ * NT_ * INNER_];
__device__ __nv_bfloat16  g_xhi[(size_t)B_ * NP_ * QD_];
__device__ __nv_bfloat16  g_xlo[(size_t)B_ * NP_ * QD_];
__device__ __nv_bfloat16  g_ahi[(size_t)B_ * NP_ * INNER_];
__device__ __nv_bfloat16  g_alo[(size_t)B_ * NP_ * INNER_];
__device__ __nv_bfloat16  g_Wthi[(size_t)QD_ * INNER_];   // weight^T hi  [N,K]
__device__ __nv_bfloat16  g_Wtlo[(size_t)QD_ * INNER_];   // weight^T lo  [N,K]

// ---------------------------------------------------------------------------
// PTX helpers (base sm_103-safe: ldmatrix + mma.sync only)
// ---------------------------------------------------------------------------
__device__ __forceinline__ uint32_t smem_u32(const void* p) {
    uint32_t a;
    asm("{ .reg .u64 t; cvta.to.shared.u64 t, %1; cvt.u32.u64 %0, t; }" : "=r"(a) : "l"(p));
    return a;
}

#define LDSM_X4(r0, r1, r2, r3, addr) \
    asm volatile("ldmatrix.sync.aligned.m8n8.x4.shared.b16 {%0,%1,%2,%3}, [%4];" \
        : "=r"(r0), "=r"(r1), "=r"(r2), "=r"(r3) : "r"(addr))

#define MMA_BF16(c0, c1, c2, c3, a0, a1, a2, a3, b0, b1) \
    asm volatile("mma.sync.aligned.m16n8k16.row.col.f32.bf16.bf16.f32 " \
        "{%0,%1,%2,%3}, {%4,%5,%6,%7}, {%8,%9}, {%0,%1,%2,%3};" \
        : "+f"(c0), "+f"(c1), "+f"(c2), "+f"(c3) \
        : "r"(a0), "r"(a1), "r"(a2), "r"(a3), "r"(b0), "r"(b1))

// smem tile layout: 128 rows x 32 bf16 (64B) per row; 16B chunks XOR-swizzled
// so that an ldmatrix gather of 8 rows hits 8 distinct 16B bank groups.
__device__ __forceinline__ uint32_t tile_off(int row, int chunk) {
    return (uint32_t)(row * 64 + ((chunk ^ ((row >> 1) & 3)) << 4));
}

// ---------------------------------------------------------------------------
// Split fp32 -> (hi, lo) bf16, same layout
// ---------------------------------------------------------------------------
__global__ __launch_bounds__(256)
void split_kernel(const float4* __restrict__ in, __nv_bfloat162* __restrict__ hi,
                  __nv_bfloat162* __restrict__ lo, int n4)
{
    int i = blockIdx.x * 256 + threadIdx.x;
    if (i >= n4) return;
    float4 v = in[i];
    __nv_bfloat16 h0 = __float2bfloat16(v.x);
    __nv_bfloat16 h1 = __float2bfloat16(v.y);
    __nv_bfloat16 h2 = __float2bfloat16(v.z);
    __nv_bfloat16 h3 = __float2bfloat16(v.w);
    __nv_bfloat16 l0 = __float2bfloat16(v.x - __bfloat162float(h0));
    __nv_bfloat16 l1 = __float2bfloat16(v.y - __bfloat162float(h1));
    __nv_bfloat16 l2 = __float2bfloat16(v.z - __bfloat162float(h2));
    __nv_bfloat16 l3 = __float2bfloat16(v.w - __bfloat162float(h3));
    hi[2 * i]     = __nv_bfloat162(h0, h1);
    hi[2 * i + 1] = __nv_bfloat162(h2, h3);
    lo[2 * i]     = __nv_bfloat162(l0, l1);
    lo[2 * i + 1] = __nv_bfloat162(l2, l3);
}

// Split + transpose weight: in [K,N] fp32 -> out [N,K] bf16 hi/lo
__global__ __launch_bounds__(256)
void splitT_kernel(const float* __restrict__ in, __nv_bfloat16* __restrict__ hiT,
                   __nv_bfloat16* __restrict__ loT, int K, int N)
{
    int i = blockIdx.x * 256 + threadIdx.x;
    if (i >= N * K) return;
    int n = i / K, k = i % K;
    float v = in[(size_t)k * N + n];
    __nv_bfloat16 h = __float2bfloat16(v);
    __nv_bfloat16 l = __float2bfloat16(v - __bfloat162float(h));
    hiT[i] = h;
    loT[i] = l;
}

// ---------------------------------------------------------------------------
// Tensor-core GEMM via mma.sync: C[M,N] = (Ahi+Alo)[M,K] @ (BThi+BTlo)^T
// BT stored [N,K]. 128x128 CTA tile, BK=32, 8 warps of 64x32, 2xBF16 split.
// Requires M%128==0, N%128==0, K%32==0.
// ---------------------------------------------------------------------------
template<bool HAS_BIAS>
__global__ __launch_bounds__(256, 2)
void mma_gemm_kernel(const __nv_bfloat16* __restrict__ Ahi, const __nv_bfloat16* __restrict__ Alo,
                     const __nv_bfloat16* __restrict__ BThi, const __nv_bfloat16* __restrict__ BTlo,
                     const float* __restrict__ bias, float* __restrict__ C,
                     int M, int N, int K)
{
    __shared__ __align__(1024) __nv_bfloat16 sAh[128 * 32];
    __shared__ __align__(1024) __nv_bfloat16 sAl[128 * 32];
    __shared__ __align__(1024) __nv_bfloat16 sBh[128 * 32];
    __shared__ __align__(1024) __nv_bfloat16 sBl[128 * 32];

    const int tid  = threadIdx.x;
    const int wid  = tid >> 5;
    const int lane = tid & 31;
    const int warp_m = wid >> 2;     // 0..1 -> 64-row slab
    const int warp_n = wid & 3;      // 0..3 -> 32-col slab
    const int m0 = blockIdx.y * 128;
    const int n0 = blockIdx.x * 128;

    const uint32_t baseAh = smem_u32(sAh);
    const uint32_t baseAl = smem_u32(sAl);
    const uint32_t baseBh = smem_u32(sBh);
    const uint32_t baseBl = smem_u32(sBl);

    float c[4][4][4];
    #pragma unroll
    for (int i = 0; i < 4; i++)
        #pragma unroll
        for (int j = 0; j < 4; j++)
            #pragma unroll
            for (int r = 0; r < 4; r++) c[i][j][r] = 0.f;

    // ldmatrix source addresses (lane-dependent, k-chunk added per step)
    // A frag fm: rows warp_m*64 + fm*16 + (lane&15), chunk kc + (lane>>4)
    // B pair fp: rows warp_n*32 + fp*16 + (lane&15), chunk kc + (lane>>4)
    const int lrow = lane & 15;
    const int lchk = lane >> 4;

    const int nchunks = K >> 5;
    for (int ch = 0; ch < nchunks; ch++) {
        const int k0 = ch << 5;

        // cooperative loads: 512 uint4 per tile, 2 per thread per tile
        #pragma unroll
        for (int t = 0; t < 2; t++) {
            const int idx = tid + t * 256;
            const int row = idx >> 2, cc = idx & 3;
            const uint32_t dst = tile_off(row, cc);
            const size_t  srcA = (size_t)(m0 + row) * K + k0 + cc * 8;
            const size_t  srcB = (size_t)(n0 + row) * K + k0 + cc * 8;
            *reinterpret_cast<uint4*>(reinterpret_cast<char*>(sAh) + dst) =
                *reinterpret_cast<const uint4*>(Ahi + srcA);
            *reinterpret_cast<uint4*>(reinterpret_cast<char*>(sAl) + dst) =
                *reinterpret_cast<const uint4*>(Alo + srcA);
            *reinterpret_cast<uint4*>(reinterpret_cast<char*>(sBh) + dst) =
                *reinterpret_cast<const uint4*>(BThi + srcB);
            *reinterpret_cast<uint4*>(reinterpret_cast<char*>(sBl) + dst) =
                *reinterpret_cast<const uint4*>(BTlo + srcB);
        }
        __syncthreads();

        #pragma unroll
        for (int ks = 0; ks < 2; ks++) {
            const int kc = ks * 2;  // 16B-chunk index of this k16 step

            uint32_t a[4][4], b1[4][2], b2[4][2];

            // ---- A hi frags + B hi frags, combo hi*hi ----
            #pragma unroll
            for (int fm = 0; fm < 4; fm++) {
                const int row = warp_m * 64 + fm * 16 + lrow;
                LDSM_X4(a[fm][0], a[fm][1], a[fm][2], a[fm][3],
                        baseAh + tile_off(row, kc + lchk));
            }
            #pragma unroll
            for (int fp = 0; fp < 2; fp++) {
                const int row = warp_n * 32 + fp * 16 + lrow;
                uint32_t r0, r1, r2, r3;
                LDSM_X4(r0, r1, r2, r3, baseBh + tile_off(row, kc + lchk));
                b1[2 * fp + 0][0] = r0; b1[2 * fp + 0][1] = r2;
                b1[2 * fp + 1][0] = r1; b1[2 * fp + 1][1] = r3;
            }
            #pragma unroll
            for (int fm = 0; fm < 4; fm++)
                #pragma unroll
                for (int fn = 0; fn < 4; fn++)
                    MMA_BF16(c[fm][fn][0], c[fm][fn][1], c[fm][fn][2], c[fm][fn][3],
                             a[fm][0], a[fm][1], a[fm][2], a[fm][3],
                             b1[fn][0], b1[fn][1]);

            // ---- B lo frags, combo hi*lo ----
            #pragma unroll
            for (int fp = 0; fp < 2; fp++) {
                const int row = warp_n * 32 + fp * 16 + lrow;
                uint32_t r0, r1, r2, r3;
                LDSM_X4(r0, r1, r2, r3, baseBl + tile_off(row, kc + lchk));
                b2[2 * fp + 0][0] = r0; b2[2 * fp + 0][1] = r2;
                b2[2 * fp + 1][0] = r1; b2[2 * fp + 1][1] = r3;
            }
            #pragma unroll
            for (int fm = 0; fm < 4; fm++)
                #pragma unroll
                for (int fn = 0; fn < 4; fn++)
                    MMA_BF16(c[fm][fn][0], c[fm][fn][1], c[fm][fn][2], c[fm][fn][3],
                             a[fm][0], a[fm][1], a[fm][2], a[fm][3],
                             b2[fn][0], b2[fn][1]);

            // ---- A lo frags, combo lo*hi ----
            #pragma unroll
            for (int fm = 0; fm < 4; fm++) {
                const int row = warp_m * 64 + fm * 16 + lrow;
                LDSM_X4(a[fm][0], a[fm][1], a[fm][2], a[fm][3],
                        baseAl + tile_off(row, kc + lchk));
            }
            #pragma unroll
            for (int fm = 0; fm < 4; fm++)
                #pragma unroll
                for (int fn = 0; fn < 4; fn++)
                    MMA_BF16(c[fm][fn][0], c[fm][fn][1], c[fm][fn][2], c[fm][fn][3],
                             a[fm][0], a[fm][1], a[fm][2], a[fm][3],
                             b1[fn][0], b1[fn][1]);
        }
        __syncthreads();
    }

    // epilogue: direct float2 stores (+bias)
    #pragma unroll
    for (int fm = 0; fm < 4; fm++) {
        const int r0 = m0 + warp_m * 64 + fm * 16 + (lane >> 2);
        #pragma unroll
        for (int fn = 0; fn < 4; fn++) {
            const int col = n0 + warp_n * 32 + fn * 8 + (lane & 3) * 2;
            float bx = 0.f, by = 0.f;
            if (HAS_BIAS) { bx = bias[col]; by = bias[col + 1]; }
            float2 v0 = make_float2(c[fm][fn][0] + bx, c[fm][fn][1] + by);
            float2 v1 = make_float2(c[fm][fn][2] + bx, c[fm][fn][3] + by);
            *reinterpret_cast<float2*>(C + (size_t)r0 * N + col) = v0;
            *reinterpret_cast<float2*>(C + (size_t)(r0 + 8) * N + col) = v1;
        }
    }
}

// ---------------------------------------------------------------------------
// fp32 SGEMM (K/V projections; M=1232)
// ---------------------------------------------------------------------------
__global__ __launch_bounds__(256, 2)
void sgemm_kernel(const float* __restrict__ A, const float* __restrict__ Bm,
                  float* __restrict__ C, int M, int N, int K)
{
    __shared__ float As[8][128];
    __shared__ float Bs[8][128];

    const int tid = threadIdx.x;
    const int m0 = blockIdx.y * 128;
    const int n0 = blockIdx.x * 128;

    const int arow = tid >> 1;
    const int acol = (tid & 1) * 4;
    const int brow = tid >> 5;
    const int bcol = (tid & 31) * 4;
    const int tx = tid & 15;
    const int ty = tid >> 4;

    float acc[8][8];
    #pragma unroll
    for (int i = 0; i < 8; i++)
        #pragma unroll
        for (int j = 0; j < 8; j++) acc[i][j] = 0.f;

    float4 ta, tb;
    if (m0 + arow < M)
        ta = *reinterpret_cast<const float4*>(A + (size_t)(m0 + arow) * K + acol);
    else
        ta = make_float4(0.f, 0.f, 0.f, 0.f);
    tb = *reinterpret_cast<const float4*>(Bm + (size_t)brow * N + n0 + bcol);
    As[acol + 0][arow] = ta.x; As[acol + 1][arow] = ta.y;
    As[acol + 2][arow] = ta.z; As[acol + 3][arow] = ta.w;
    *reinterpret_cast<float4*>(&Bs[brow][bcol]) = tb;
    __syncthreads();

    const int ntiles = K >> 3;
    for (int t = 0; t < ntiles; t++) {
        const int knext = (t + 1) << 3;
        if (t + 1 < ntiles) {
            if (m0 + arow < M)
                ta = *reinterpret_cast<const float4*>(A + (size_t)(m0 + arow) * K + knext + acol);
            else
                ta = make_float4(0.f, 0.f, 0.f, 0.f);
            tb = *reinterpret_cast<const float4*>(Bm + (size_t)(knext + brow) * N + n0 + bcol);
        }
        #pragma unroll
        for (int k = 0; k < 8; k++) {
            float ra[8], rb[8];
            *reinterpret_cast<float4*>(&ra[0]) = *reinterpret_cast<const float4*>(&As[k][ty * 8]);
            *reinterpret_cast<float4*>(&ra[4]) = *reinterpret_cast<const float4*>(&As[k][ty * 8 + 4]);
            *reinterpret_cast<float4*>(&rb[0]) = *reinterpret_cast<const float4*>(&Bs[k][tx * 8]);
            *reinterpret_cast<float4*>(&rb[4]) = *reinterpret_cast<const float4*>(&Bs[k][tx * 8 + 4]);
            #pragma unroll
            for (int i = 0; i < 8; i++)
                #pragma unroll
                for (int j = 0; j < 8; j++)
                    acc[i][j] += ra[i] * rb[j];
        }
        __syncthreads();
        if (t + 1 < ntiles) {
            As[acol + 0][arow] = ta.x; As[acol + 1][arow] = ta.y;
            As[acol + 2][arow] = ta.z; As[acol + 3][arow] = ta.w;
            *reinterpret_cast<float4*>(&Bs[brow][bcol]) = tb;
        }
        __syncthreads();
    }

    #pragma unroll
    for (int i = 0; i < 8; i++) {
        const int row = m0 + ty * 8 + i;
        if (row < M) {
            float* cp = C + (size_t)row * N + n0 + tx * 8;
            #pragma unroll
            for (int j = 0; j < 8; j += 4) {
                float4 v;
                v.x = acc[i][j + 0]; v.y = acc[i][j + 1];
                v.z = acc[i][j + 2]; v.w = acc[i][j + 3];
                *reinterpret_cast<float4*>(cp + j) = v;
            }
        }
    }
}

// ---------------------------------------------------------------------------
// Fused attention: 2 threads per q-row (each owns 32 of 64 dims).
// Writes hi/lo bf16 directly for the O-projection.
// ---------------------------------------------------------------------------
__global__ __launch_bounds__(256, 2)
void attn_kernel(const float* __restrict__ Q, const float* __restrict__ Kb,
                 const float* __restrict__ Vb, const int* __restrict__ mask,
                 __nv_bfloat16* __restrict__ Ohi, __nv_bfloat16* __restrict__ Olo)
{
    __shared__ float Ks[NT_][DH_];
    __shared__ float Vs[NT_][DH_];

    const int b = blockIdx.z;
    const int h = blockIdx.y;
    const int tid = threadIdx.x;
    const int half = tid & 1;                 // which 32-dim half
    const int qr = blockIdx.x * 128 + (tid >> 1);

    for (int i = tid; i < NT_ * DH_; i += 256) {
        const int j = i >> 6;
        const int d = i & 63;
        const size_t src = ((size_t)(b * NT_ + j)) * INNER_ + h * DH_ + d;
        Ks[j][d] = Kb[src];
        Vs[j][d] = Vb[src];
    }
    __syncthreads();

    float q[32];
    const float4* qp = reinterpret_cast<const float4*>(
        Q + ((size_t)(b * NP_ + qr)) * INNER_ + h * DH_ + half * 32);
    #pragma unroll
    for (int i = 0; i < 8; i++) {
        float4 v = qp[i];
        q[4 * i + 0] = v.x; q[4 * i + 1] = v.y;
        q[4 * i + 2] = v.z; q[4 * i + 3] = v.w;
    }

    const int* mrow = mask + ((size_t)(b * NP_ + qr)) * NT_;

    float acc[32];
    #pragma unroll
    for (int d = 0; d < 32; d++) acc[d] = 0.f;
    float l = 0.f;

    #pragma unroll 1
    for (int j = 0; j < NT_; j++) {
        const float4* kj = reinterpret_cast<const float4*>(&Ks[j][half * 32]);
        float s0 = 0.f, s1 = 0.f, s2 = 0.f, s3 = 0.f;
        #pragma unroll
        for (int d4 = 0; d4 < 8; d4++) {
            float4 kv = kj[d4];
            s0 += q[4 * d4 + 0] * kv.x;
            s1 += q[4 * d4 + 1] * kv.y;
            s2 += q[4 * d4 + 2] * kv.z;
            s3 += q[4 * d4 + 3] * kv.w;
        }
        float s = (s0 + s1) + (s2 + s3);
        s += __shfl_xor_sync(0xFFFFFFFF, s, 1);   // fold the other half
        s *= 0.125f;                               // 1/sqrt(64)
        const float e = (mrow[j] != 0) ? __expf(s) : 0.f;
        l += e;
        const float4* vj = reinterpret_cast<const float4*>(&Vs[j][half * 32]);
        #pragma unroll
        for (int d4 = 0; d4 < 8; d4++) {
            float4 vv = vj[d4];
            acc[4 * d4 + 0] += e * vv.x;
            acc[4 * d4 + 1] += e * vv.y;
            acc[4 * d4 + 2] += e * vv.z;
            acc[4 * d4 + 3] += e * vv.w;
        }
    }

    const float inv = 1.f / l;
    const size_t obase = ((size_t)(b * NP_ + qr)) * INNER_ + h * DH_ + half * 32;
    __nv_bfloat162* ph = reinterpret_cast<__nv_bfloat162*>(Ohi + obase);
    __nv_bfloat162* pl = reinterpret_cast<__nv_bfloat162*>(Olo + obase);
    #pragma unroll
    for (int d = 0; d < 32; d += 2) {
        const float o0 = acc[d] * inv;
        const float o1 = acc[d + 1] * inv;
        const __nv_bfloat16 h0 = __float2bfloat16(o0);
        const __nv_bfloat16 h1 = __float2bfloat16(o1);
        const __nv_bfloat16 l0 = __float2bfloat16(o0 - __bfloat162float(h0));
        const __nv_bfloat16 l1 = __float2bfloat16(o1 - __bfloat162float(h1));
        ph[d >> 1] = __nv_bfloat162(h0, h1);
        pl[d >> 1] = __nv_bfloat162(l0, l1);
    }
}

// ---------------------------------------------------------------------------
// Launch
// ---------------------------------------------------------------------------
extern "C" void kernel_launch(void* const* d_in, const int* in_sizes, int n_in,
                              void* d_out, int out_size)
{
    const float* x    = (const float*)d_in[0];
    const float* ctx  = (const float*)d_in[1];
    const int*   mask = (const int*)  d_in[2];
    const float* Wq   = (const float*)d_in[3];
    const float* Wk   = (const float*)d_in[4];
    const float* Wv   = (const float*)d_in[5];
    const float* Wo   = (const float*)d_in[6];
    const float* bo   = (const float*)d_in[7];
    float* out = (float*)d_out;

    float *Qb, *Kb, *Vb;
    __nv_bfloat16 *xhi, *xlo, *ahi, *alo, *wthi, *wtlo;
    cudaGetSymbolAddress((void**)&Qb,   g_Q);
    cudaGetSymbolAddress((void**)&Kb,   g_Kp);
    cudaGetSymbolAddress((void**)&Vb,   g_Vp);
    cudaGetSymbolAddress((void**)&xhi,  g_xhi);
    cudaGetSymbolAddress((void**)&xlo,  g_xlo);
    cudaGetSymbolAddress((void**)&ahi,  g_ahi);
    cudaGetSymbolAddress((void**)&alo,  g_alo);
    cudaGetSymbolAddress((void**)&wthi, g_Wthi);
    cudaGetSymbolAddress((void**)&wtlo, g_Wtlo);

    const int Mq = B_ * NP_;   // 65536
    const int Mc = B_ * NT_;   // 1232

    // split x -> bf16 hi/lo
    {
        const int n4 = Mq * QD_ / 4;
        split_kernel<<<(n4 + 255) / 256, 256>>>(
            (const float4*)x, (__nv_bfloat162*)xhi, (__nv_bfloat162*)xlo, n4);
    }
    // split+transpose Wq
    splitT_kernel<<<(QD_ * INNER_ + 255) / 256, 256>>>(Wq, wthi, wtlo, QD_, INNER_);

    // Q = x @ Wq  (mma.sync bf16, 2xBF16 split)
    mma_gemm_kernel<false><<<dim3(INNER_ / 128, Mq / 128), 256>>>(
        xhi, xlo, wthi, wtlo, nullptr, Qb, Mq, INNER_, QD_);

    // K/V projections (fp32)
    sgemm_kernel<<<dim3(INNER_ / 128, (Mc + 127) / 128), 256>>>(ctx, Wk, Kb, Mc, INNER_, CD_);
    sgemm_kernel<<<dim3(INNER_ / 128, (Mc + 127) / 128), 256>>>(ctx, Wv, Vb, Mc, INNER_, CD_);

    // fused attention -> bf16 hi/lo
    attn_kernel<<<dim3(NP_ / 128, H_, B_), 256>>>(Qb, Kb, Vb, mask, ahi, alo);

    // split+transpose Wo (stream-ordered reuse of weight buffers)
    splitT_kernel<<<(INNER_ * QD_ + 255) / 256, 256>>>(Wo, wthi, wtlo, INNER_, QD_);

    // out = Att @ Wo + bo  (mma.sync bf16, 2xBF16 split)
    mma_gemm_kernel<true><<<dim3(QD_ / 128, Mq / 128), 256>>>(
        ahi, alo, wthi, wtlo, bo, out, Mq, QD_, INNER_);
}

// round 4
// speedup vs baseline: 1.7926x; 1.2251x over previous
#include <cuda_runtime.h>
#include <cuda_bf16.h>
#include <cstdint>

// Problem constants
#define B_   16
#define NP_  4096
#define NT_  77
#define QD_  512
#define CD_  768
#define H_   8
#define DH_  64
#define INNER_ 512   // H*DH

typedef __nv_bfloat16 bf16;

// ---------------------------------------------------------------------------
// Scratch (device globals)
// ---------------------------------------------------------------------------
__device__ float g_Q  [(size_t)B_ * NP_ * INNER_];
__device__ float g_Kp [(size_t)B_ * NT_ * INNER_];
__device__ float g_Vp [(size_t)B_ * NT_ * INNER_];
__device__ bf16  g_xhi[(size_t)B_ * NP_ * QD_];
__device__ bf16  g_xlo[(size_t)B_ * NP_ * QD_];
__device__ bf16  g_ahi[(size_t)B_ * NP_ * INNER_];
__device__ bf16  g_alo[(size_t)B_ * NP_ * INNER_];
__device__ bf16  g_Wthi[(size_t)QD_ * INNER_];    // Wq^T / Wo^T hi  [N,K]
__device__ bf16  g_Wtlo[(size_t)QD_ * INNER_];
__device__ bf16  g_chi [(size_t)B_ * NT_ * CD_];  // ctx hi/lo
__device__ bf16  g_clo [(size_t)B_ * NT_ * CD_];
__device__ bf16  g_WkThi[(size_t)CD_ * INNER_];
__device__ bf16  g_WkTlo[(size_t)CD_ * INNER_];
__device__ bf16  g_WvThi[(size_t)CD_ * INNER_];
__device__ bf16  g_WvTlo[(size_t)CD_ * INNER_];

// ---------------------------------------------------------------------------
// PTX helpers (base sm_103-safe: ldmatrix / mma.sync / cp.async)
// ---------------------------------------------------------------------------
__device__ __forceinline__ uint32_t smem_u32(const void* p) {
    uint32_t a;
    asm("{ .reg .u64 t; cvta.to.shared.u64 t, %1; cvt.u32.u64 %0, t; }" : "=r"(a) : "l"(p));
    return a;
}

#define LDSM_X4(r0, r1, r2, r3, addr) \
    asm volatile("ldmatrix.sync.aligned.m8n8.x4.shared.b16 {%0,%1,%2,%3}, [%4];" \
        : "=r"(r0), "=r"(r1), "=r"(r2), "=r"(r3) : "r"(addr))

#define MMA_BF16(c0, c1, c2, c3, a0, a1, a2, a3, b0, b1) \
    asm volatile("mma.sync.aligned.m16n8k16.row.col.f32.bf16.bf16.f32 " \
        "{%0,%1,%2,%3}, {%4,%5,%6,%7}, {%8,%9}, {%0,%1,%2,%3};" \
        : "+f"(c0), "+f"(c1), "+f"(c2), "+f"(c3) \
        : "r"(a0), "r"(a1), "r"(a2), "r"(a3), "r"(b0), "r"(b1))

#define CP_ASYNC16(dst, src) \
    asm volatile("cp.async.cg.shared.global [%0], [%1], 16;" :: "r"(dst), "l"(src))
#define CP_COMMIT() asm volatile("cp.async.commit_group;" ::: "memory")
#define CP_WAIT1()  asm volatile("cp.async.wait_group 1;" ::: "memory")
#define CP_WAIT0()  asm volatile("cp.async.wait_group 0;" ::: "memory")

// smem tile: 128 rows x 32 bf16 (64B/row); 16B chunks XOR-swizzled so an
// ldmatrix gather of 8 rows hits 8 distinct 16B bank groups.
__device__ __forceinline__ uint32_t tile_off(int row, int chunk) {
    return (uint32_t)(row * 64 + ((chunk ^ ((row >> 1) & 3)) << 4));
}

// ---------------------------------------------------------------------------
// Split fp32 -> (hi, lo) bf16
// ---------------------------------------------------------------------------
__global__ __launch_bounds__(256)
void split_kernel(const float4* __restrict__ in, __nv_bfloat162* __restrict__ hi,
                  __nv_bfloat162* __restrict__ lo, int n4)
{
    int i = blockIdx.x * 256 + threadIdx.x;
    if (i >= n4) return;
    float4 v = in[i];
    bf16 h0 = __float2bfloat16(v.x);
    bf16 h1 = __float2bfloat16(v.y);
    bf16 h2 = __float2bfloat16(v.z);
    bf16 h3 = __float2bfloat16(v.w);
    bf16 l0 = __float2bfloat16(v.x - __bfloat162float(h0));
    bf16 l1 = __float2bfloat16(v.y - __bfloat162float(h1));
    bf16 l2 = __float2bfloat16(v.z - __bfloat162float(h2));
    bf16 l3 = __float2bfloat16(v.w - __bfloat162float(h3));
    hi[2 * i]     = __nv_bfloat162(h0, h1);
    hi[2 * i + 1] = __nv_bfloat162(h2, h3);
    lo[2 * i]     = __nv_bfloat162(l0, l1);
    lo[2 * i + 1] = __nv_bfloat162(l2, l3);
}

// Split + transpose weight: in [K,N] fp32 -> out [N,K] bf16 hi/lo
__global__ __launch_bounds__(256)
void splitT_kernel(const float* __restrict__ in, bf16* __restrict__ hiT,
                   bf16* __restrict__ loT, int K, int N)
{
    int i = blockIdx.x * 256 + threadIdx.x;
    if (i >= N * K) return;
    int n = i / K, k = i % K;
    float v = in[(size_t)k * N + n];
    bf16 h = __float2bfloat16(v);
    bf16 l = __float2bfloat16(v - __bfloat162float(h));
    hiT[i] = h;
    loT[i] = l;
}

// ---------------------------------------------------------------------------
// Pipelined mma.sync GEMM: C[M,N] = (Ahi+Alo)[M,K] @ (BThi+BTlo)^T
// BT stored [N,K]. 128x128 CTA tile, BK=32, cp.async double-buffered,
// 2xBF16 split (hi*hi + hi*lo + lo*hi). gridDim.z selects B/C set (for fused
// K+V projection). A rows clamped to M-1; C stores guarded (M%128 free).
// N%128==0, K%32==0 required.
// ---------------------------------------------------------------------------
#define STG_A_HI 0
#define STG_A_LO 8192
#define STG_B_HI 16384
#define STG_B_LO 24576
#define STG_SIZE 32768
#define PIPE_SMEM (2 * STG_SIZE)

template<bool HAS_BIAS>
__global__ __launch_bounds__(256, 2)
void mma_gemm_pipe(const bf16* __restrict__ Ahi, const bf16* __restrict__ Alo,
                   const bf16* __restrict__ B0hi, const bf16* __restrict__ B0lo, float* __restrict__ C0,
                   const bf16* __restrict__ B1hi, const bf16* __restrict__ B1lo, float* __restrict__ C1,
                   const float* __restrict__ bias, int M, int N, int K)
{
    extern __shared__ __align__(1024) char dsm[];
    const uint32_t smem_base = smem_u32(dsm);

    const bf16* BThi = blockIdx.z ? B1hi : B0hi;
    const bf16* BTlo = blockIdx.z ? B1lo : B0lo;
    float*      C    = blockIdx.z ? C1   : C0;

    const int tid  = threadIdx.x;
    const int wid  = tid >> 5;
    const int lane = tid & 31;
    const int warp_m = wid >> 2;     // 0..1 -> 64-row slab
    const int warp_n = wid & 3;      // 0..3 -> 32-col slab
    const int m0 = blockIdx.y * 128;
    const int n0 = blockIdx.x * 128;

    float c[4][4][4];
    #pragma unroll
    for (int i = 0; i < 4; i++)
        #pragma unroll
        for (int j = 0; j < 4; j++)
            #pragma unroll
            for (int r = 0; r < 4; r++) c[i][j][r] = 0.f;

    const int lrow = lane & 15;
    const int lchk = lane >> 4;
    const int nchunks = K >> 5;

    // --- async load of one chunk into stage s ---
    auto load_chunk = [&](int s, int k0) {
        const uint32_t sb = smem_base + s * STG_SIZE;
        #pragma unroll
        for (int t = 0; t < 2; t++) {
            const int idx = tid + t * 256;
            const int row = idx >> 2, cc = idx & 3;
            const uint32_t off = tile_off(row, cc);
            const int ar = min(m0 + row, M - 1);
            const size_t aidx = (size_t)ar * K + k0 + cc * 8;
            const size_t bidx = (size_t)(n0 + row) * K + k0 + cc * 8;
            CP_ASYNC16(sb + STG_A_HI + off, Ahi + aidx);
            CP_ASYNC16(sb + STG_A_LO + off, Alo + aidx);
            CP_ASYNC16(sb + STG_B_HI + off, BThi + bidx);
            CP_ASYNC16(sb + STG_B_LO + off, BTlo + bidx);
        }
        CP_COMMIT();
    };

    load_chunk(0, 0);

    for (int ch = 0; ch < nchunks; ch++) {
        if (ch + 1 < nchunks) {
            load_chunk((ch + 1) & 1, (ch + 1) << 5);
            CP_WAIT1();
        } else {
            CP_WAIT0();
        }
        __syncthreads();

        const uint32_t sb = smem_base + (ch & 1) * STG_SIZE;

        #pragma unroll
        for (int ks = 0; ks < 2; ks++) {
            const int kc = ks * 2;
            uint32_t a[4][4], b1[4][2], b2[4][2];

            // A hi + B hi -> hi*hi
            #pragma unroll
            for (int fm = 0; fm < 4; fm++) {
                const int row = warp_m * 64 + fm * 16 + lrow;
                LDSM_X4(a[fm][0], a[fm][1], a[fm][2], a[fm][3],
                        sb + STG_A_HI + tile_off(row, kc + lchk));
            }
            #pragma unroll
            for (int fp = 0; fp < 2; fp++) {
                const int row = warp_n * 32 + fp * 16 + lrow;
                uint32_t r0, r1, r2, r3;
                LDSM_X4(r0, r1, r2, r3, sb + STG_B_HI + tile_off(row, kc + lchk));
                b1[2 * fp + 0][0] = r0; b1[2 * fp + 0][1] = r2;
                b1[2 * fp + 1][0] = r1; b1[2 * fp + 1][1] = r3;
            }
            #pragma unroll
            for (int fm = 0; fm < 4; fm++)
                #pragma unroll
                for (int fn = 0; fn < 4; fn++)
                    MMA_BF16(c[fm][fn][0], c[fm][fn][1], c[fm][fn][2], c[fm][fn][3],
                             a[fm][0], a[fm][1], a[fm][2], a[fm][3],
                             b1[fn][0], b1[fn][1]);

            // B lo -> hi*lo
            #pragma unroll
            for (int fp = 0; fp < 2; fp++) {
                const int row = warp_n * 32 + fp * 16 + lrow;
                uint32_t r0, r1, r2, r3;
                LDSM_X4(r0, r1, r2, r3, sb + STG_B_LO + tile_off(row, kc + lchk));
                b2[2 * fp + 0][0] = r0; b2[2 * fp + 0][1] = r2;
                b2[2 * fp + 1][0] = r1; b2[2 * fp + 1][1] = r3;
            }
            #pragma unroll
            for (int fm = 0; fm < 4; fm++)
                #pragma unroll
                for (int fn = 0; fn < 4; fn++)
                    MMA_BF16(c[fm][fn][0], c[fm][fn][1], c[fm][fn][2], c[fm][fn][3],
                             a[fm][0], a[fm][1], a[fm][2], a[fm][3],
                             b2[fn][0], b2[fn][1]);

            // A lo -> lo*hi
            #pragma unroll
            for (int fm = 0; fm < 4; fm++) {
                const int row = warp_m * 64 + fm * 16 + lrow;
                LDSM_X4(a[fm][0], a[fm][1], a[fm][2], a[fm][3],
                        sb + STG_A_LO + tile_off(row, kc + lchk));
            }
            #pragma unroll
            for (int fm = 0; fm < 4; fm++)
                #pragma unroll
                for (int fn = 0; fn < 4; fn++)
                    MMA_BF16(c[fm][fn][0], c[fm][fn][1], c[fm][fn][2], c[fm][fn][3],
                             a[fm][0], a[fm][1], a[fm][2], a[fm][3],
                             b1[fn][0], b1[fn][1]);
        }
        __syncthreads();
    }

    // epilogue (+bias, guarded rows)
    #pragma unroll
    for (int fm = 0; fm < 4; fm++) {
        const int r0 = m0 + warp_m * 64 + fm * 16 + (lane >> 2);
        #pragma unroll
        for (int fn = 0; fn < 4; fn++) {
            const int col = n0 + warp_n * 32 + fn * 8 + (lane & 3) * 2;
            float bx = 0.f, by = 0.f;
            if (HAS_BIAS) { bx = bias[col]; by = bias[col + 1]; }
            if (r0 < M) {
                float2 v0 = make_float2(c[fm][fn][0] + bx, c[fm][fn][1] + by);
                *reinterpret_cast<float2*>(C + (size_t)r0 * N + col) = v0;
            }
            if (r0 + 8 < M) {
                float2 v1 = make_float2(c[fm][fn][2] + bx, c[fm][fn][3] + by);
                *reinterpret_cast<float2*>(C + (size_t)(r0 + 8) * N + col) = v1;
            }
        }
    }
}

// ---------------------------------------------------------------------------
// Fused attention: 2 threads per q-row (each owns 32 of 64 dims).
// Writes hi/lo bf16 directly for the O-projection.
// ---------------------------------------------------------------------------
__global__ __launch_bounds__(256, 2)
void attn_kernel(const float* __restrict__ Q, const float* __restrict__ Kb,
                 const float* __restrict__ Vb, const int* __restrict__ mask,
                 bf16* __restrict__ Ohi, bf16* __restrict__ Olo)
{
    __shared__ float Ks[NT_][DH_];
    __shared__ float Vs[NT_][DH_];

    const int b = blockIdx.z;
    const int h = blockIdx.y;
    const int tid = threadIdx.x;
    const int half = tid & 1;
    const int qr = blockIdx.x * 128 + (tid >> 1);

    for (int i = tid; i < NT_ * DH_; i += 256) {
        const int j = i >> 6;
        const int d = i & 63;
        const size_t src = ((size_t)(b * NT_ + j)) * INNER_ + h * DH_ + d;
        Ks[j][d] = Kb[src];
        Vs[j][d] = Vb[src];
    }
    __syncthreads();

    float q[32];
    const float4* qp = reinterpret_cast<const float4*>(
        Q + ((size_t)(b * NP_ + qr)) * INNER_ + h * DH_ + half * 32);
    #pragma unroll
    for (int i = 0; i < 8; i++) {
        float4 v = qp[i];
        q[4 * i + 0] = v.x; q[4 * i + 1] = v.y;
        q[4 * i + 2] = v.z; q[4 * i + 3] = v.w;
    }

    const int* mrow = mask + ((size_t)(b * NP_ + qr)) * NT_;

    float acc[32];
    #pragma unroll
    for (int d = 0; d < 32; d++) acc[d] = 0.f;
    float l = 0.f;

    #pragma unroll 1
    for (int j = 0; j < NT_; j++) {
        const float4* kj = reinterpret_cast<const float4*>(&Ks[j][half * 32]);
        float s0 = 0.f, s1 = 0.f, s2 = 0.f, s3 = 0.f;
        #pragma unroll
        for (int d4 = 0; d4 < 8; d4++) {
            float4 kv = kj[d4];
            s0 += q[4 * d4 + 0] * kv.x;
            s1 += q[4 * d4 + 1] * kv.y;
            s2 += q[4 * d4 + 2] * kv.z;
            s3 += q[4 * d4 + 3] * kv.w;
        }
        float s = (s0 + s1) + (s2 + s3);
        s += __shfl_xor_sync(0xFFFFFFFF, s, 1);
        s *= 0.125f;
        const float e = (mrow[j] != 0) ? __expf(s) : 0.f;
        l += e;
        const float4* vj = reinterpret_cast<const float4*>(&Vs[j][half * 32]);
        #pragma unroll
        for (int d4 = 0; d4 < 8; d4++) {
            float4 vv = vj[d4];
            acc[4 * d4 + 0] += e * vv.x;
            acc[4 * d4 + 1] += e * vv.y;
            acc[4 * d4 + 2] += e * vv.z;
            acc[4 * d4 + 3] += e * vv.w;
        }
    }

    const float inv = 1.f / l;
    const size_t obase = ((size_t)(b * NP_ + qr)) * INNER_ + h * DH_ + half * 32;
    __nv_bfloat162* ph = reinterpret_cast<__nv_bfloat162*>(Ohi + obase);
    __nv_bfloat162* pl = reinterpret_cast<__nv_bfloat162*>(Olo + obase);
    #pragma unroll
    for (int d = 0; d < 32; d += 2) {
        const float o0 = acc[d] * inv;
        const float o1 = acc[d + 1] * inv;
        const bf16 h0 = __float2bfloat16(o0);
        const bf16 h1 = __float2bfloat16(o1);
        const bf16 l0 = __float2bfloat16(o0 - __bfloat162float(h0));
        const bf16 l1 = __float2bfloat16(o1 - __bfloat162float(h1));
        ph[d >> 1] = __nv_bfloat162(h0, h1);
        pl[d >> 1] = __nv_bfloat162(l0, l1);
    }
}

// ---------------------------------------------------------------------------
// Launch
// ---------------------------------------------------------------------------
extern "C" void kernel_launch(void* const* d_in, const int* in_sizes, int n_in,
                              void* d_out, int out_size)
{
    const float* x    = (const float*)d_in[0];
    const float* ctx  = (const float*)d_in[1];
    const int*   mask = (const int*)  d_in[2];
    const float* Wq   = (const float*)d_in[3];
    const float* Wk   = (const float*)d_in[4];
    const float* Wv   = (const float*)d_in[5];
    const float* Wo   = (const float*)d_in[6];
    const float* bo   = (const float*)d_in[7];
    float* out = (float*)d_out;

    float *Qb, *Kb, *Vb;
    bf16 *xhi, *xlo, *ahi, *alo, *wthi, *wtlo, *chi, *clo;
    bf16 *wkhi, *wklo, *wvhi, *wvlo;
    cudaGetSymbolAddress((void**)&Qb,   g_Q);
    cudaGetSymbolAddress((void**)&Kb,   g_Kp);
    cudaGetSymbolAddress((void**)&Vb,   g_Vp);
    cudaGetSymbolAddress((void**)&xhi,  g_xhi);
    cudaGetSymbolAddress((void**)&xlo,  g_xlo);
    cudaGetSymbolAddress((void**)&ahi,  g_ahi);
    cudaGetSymbolAddress((void**)&alo,  g_alo);
    cudaGetSymbolAddress((void**)&wthi, g_Wthi);
    cudaGetSymbolAddress((void**)&wtlo, g_Wtlo);
    cudaGetSymbolAddress((void**)&chi,  g_chi);
    cudaGetSymbolAddress((void**)&clo,  g_clo);
    cudaGetSymbolAddress((void**)&wkhi, g_WkThi);
    cudaGetSymbolAddress((void**)&wklo, g_WkTlo);
    cudaGetSymbolAddress((void**)&wvhi, g_WvThi);
    cudaGetSymbolAddress((void**)&wvlo, g_WvTlo);

    cudaFuncSetAttribute(mma_gemm_pipe<false>,
                         cudaFuncAttributeMaxDynamicSharedMemorySize, PIPE_SMEM);
    cudaFuncSetAttribute(mma_gemm_pipe<true>,
                         cudaFuncAttributeMaxDynamicSharedMemorySize, PIPE_SMEM);

    const int Mq = B_ * NP_;   // 65536
    const int Mc = B_ * NT_;   // 1232

    // splits
    {
        const int n4 = Mq * QD_ / 4;
        split_kernel<<<(n4 + 255) / 256, 256>>>(
            (const float4*)x, (__nv_bfloat162*)xhi, (__nv_bfloat162*)xlo, n4);
    }
    {
        const int n4 = Mc * CD_ / 4;
        split_kernel<<<(n4 + 255) / 256, 256>>>(
            (const float4*)ctx, (__nv_bfloat162*)chi, (__nv_bfloat162*)clo, n4);
    }
    splitT_kernel<<<(QD_ * INNER_ + 255) / 256, 256>>>(Wq, wthi, wtlo, QD_, INNER_);
    splitT_kernel<<<(CD_ * INNER_ + 255) / 256, 256>>>(Wk, wkhi, wklo, CD_, INNER_);
    splitT_kernel<<<(CD_ * INNER_ + 255) / 256, 256>>>(Wv, wvhi, wvlo, CD_, INNER_);

    // Q = x @ Wq
    mma_gemm_pipe<false><<<dim3(INNER_ / 128, Mq / 128, 1), 256, PIPE_SMEM>>>(
        xhi, xlo, wthi, wtlo, Qb, wthi, wtlo, Qb, nullptr, Mq, INNER_, QD_);

    // K = ctx @ Wk, V = ctx @ Wv  (fused via gridDim.z)
    mma_gemm_pipe<false><<<dim3(INNER_ / 128, (Mc + 127) / 128, 2), 256, PIPE_SMEM>>>(
        chi, clo, wkhi, wklo, Kb, wvhi, wvlo, Vb, nullptr, Mc, INNER_, CD_);

    // fused attention -> bf16 hi/lo
    attn_kernel<<<dim3(NP_ / 128, H_, B_), 256>>>(Qb, Kb, Vb, mask, ahi, alo);

    // split+transpose Wo (stream-ordered reuse)
    splitT_kernel<<<(INNER_ * QD_ + 255) / 256, 256>>>(Wo, wthi, wtlo, INNER_, QD_);

    // out = Att @ Wo + bo
    mma_gemm_pipe<true><<<dim3(QD_ / 128, Mq / 128, 1), 256, PIPE_SMEM>>>(
        ahi, alo, wthi, wtlo, out, wthi, wtlo, out, bo, Mq, QD_, INNER_);
}

// round 5
// speedup vs baseline: 2.5550x; 1.4253x over previous
#include <cuda_runtime.h>
#include <cuda_fp16.h>
#include <cstdint>

// Problem constants
#define B_   16
#define NP_  4096
#define NT_  77
#define QD_  512
#define CD_  768
#define H_   8
#define DH_  64
#define INNER_ 512   // H*DH

// ---------------------------------------------------------------------------
// Scratch (device globals)
// ---------------------------------------------------------------------------
__device__ float  g_Q  [(size_t)B_ * NP_ * INNER_];
__device__ float  g_Kp [(size_t)B_ * NT_ * INNER_];
__device__ float  g_Vp [(size_t)B_ * NT_ * INNER_];
__device__ __half g_xh [(size_t)B_ * NP_ * QD_];
__device__ __half g_ah [(size_t)B_ * NP_ * INNER_];
__device__ __half g_ch [(size_t)B_ * NT_ * CD_];
__device__ __half g_Wt [(size_t)QD_ * INNER_];    // Wq^T / Wo^T  [N,K]
__device__ __half g_WkT[(size_t)CD_ * INNER_];
__device__ __half g_WvT[(size_t)CD_ * INNER_];

// ---------------------------------------------------------------------------
// PTX helpers (base sm_103-safe: ldmatrix / mma.sync / cp.async)
// ---------------------------------------------------------------------------
__device__ __forceinline__ uint32_t smem_u32(const void* p) {
    uint32_t a;
    asm("{ .reg .u64 t; cvta.to.shared.u64 t, %1; cvt.u32.u64 %0, t; }" : "=r"(a) : "l"(p));
    return a;
}

#define LDSM_X4(r0, r1, r2, r3, addr) \
    asm volatile("ldmatrix.sync.aligned.m8n8.x4.shared.b16 {%0,%1,%2,%3}, [%4];" \
        : "=r"(r0), "=r"(r1), "=r"(r2), "=r"(r3) : "r"(addr))

#define MMA_F16(c0, c1, c2, c3, a0, a1, a2, a3, b0, b1) \
    asm volatile("mma.sync.aligned.m16n8k16.row.col.f32.f16.f16.f32 " \
        "{%0,%1,%2,%3}, {%4,%5,%6,%7}, {%8,%9}, {%0,%1,%2,%3};" \
        : "+f"(c0), "+f"(c1), "+f"(c2), "+f"(c3) \
        : "r"(a0), "r"(a1), "r"(a2), "r"(a3), "r"(b0), "r"(b1))

#define CP_ASYNC16(dst, src) \
    asm volatile("cp.async.cg.shared.global [%0], [%1], 16;" :: "r"(dst), "l"(src))
#define CP_COMMIT() asm volatile("cp.async.commit_group;" ::: "memory")
#define CP_WAIT1()  asm volatile("cp.async.wait_group 1;" ::: "memory")
#define CP_WAIT0()  asm volatile("cp.async.wait_group 0;" ::: "memory")

// smem tile: 128 rows x 32 fp16 (64B/row); 16B chunks XOR-swizzled so an
// ldmatrix gather of 8 rows hits 8 distinct 16B bank groups.
__device__ __forceinline__ uint32_t tile_off(int row, int chunk) {
    return (uint32_t)(row * 64 + ((chunk ^ ((row >> 1) & 3)) << 4));
}

// ---------------------------------------------------------------------------
// fp32 -> fp16 conversion
// ---------------------------------------------------------------------------
__global__ __launch_bounds__(256)
void tohalf_kernel(const float4* __restrict__ in, __half2* __restrict__ out, int n4)
{
    int i = blockIdx.x * 256 + threadIdx.x;
    if (i >= n4) return;
    float4 v = in[i];
    out[2 * i]     = __floats2half2_rn(v.x, v.y);
    out[2 * i + 1] = __floats2half2_rn(v.z, v.w);
}

// transpose + convert weight: in [K,N] fp32 -> out [N,K] fp16
__global__ __launch_bounds__(256)
void transT_kernel(const float* __restrict__ in, __half* __restrict__ outT, int K, int N)
{
    int i = blockIdx.x * 256 + threadIdx.x;
    if (i >= N * K) return;
    int n = i / K, k = i % K;
    outT[i] = __float2half_rn(in[(size_t)k * N + n]);
}

// ---------------------------------------------------------------------------
// Pipelined fp16 mma.sync GEMM: C[M,N] = A[M,K] @ BT[N,K]^T  (fp32 accum/out)
// 128x128 CTA tile, BK=32, 3-stage cp.async pipeline, 8 warps of 64x32.
// gridDim.z selects B/C set (fused K+V projection). A rows clamped; C guarded.
// N%128==0, K%32==0 required.
// ---------------------------------------------------------------------------
#define STG_A 0
#define STG_B 8192
#define STG_SIZE 16384
#define NSTAGE 3
#define PIPE_SMEM (NSTAGE * STG_SIZE)

template<bool HAS_BIAS>
__global__ __launch_bounds__(256, 2)
void mma_gemm_pipe(const __half* __restrict__ A,
                   const __half* __restrict__ B0, float* __restrict__ C0,
                   const __half* __restrict__ B1, float* __restrict__ C1,
                   const float* __restrict__ bias, int M, int N, int K)
{
    extern __shared__ __align__(1024) char dsm[];
    const uint32_t smem_base = smem_u32(dsm);

    const __half* BT = blockIdx.z ? B1 : B0;
    float*        C  = blockIdx.z ? C1 : C0;

    const int tid  = threadIdx.x;
    const int wid  = tid >> 5;
    const int lane = tid & 31;
    const int warp_m = wid >> 2;     // 0..1 -> 64-row slab
    const int warp_n = wid & 3;      // 0..3 -> 32-col slab
    const int m0 = blockIdx.y * 128;
    const int n0 = blockIdx.x * 128;

    float c[4][4][4];
    #pragma unroll
    for (int i = 0; i < 4; i++)
        #pragma unroll
        for (int j = 0; j < 4; j++)
            #pragma unroll
            for (int r = 0; r < 4; r++) c[i][j][r] = 0.f;

    const int lrow = lane & 15;
    const int lchk = lane >> 4;
    const int nchunks = K >> 5;

    auto load_chunk = [&](int s, int k0) {
        const uint32_t sb = smem_base + s * STG_SIZE;
        #pragma unroll
        for (int t = 0; t < 2; t++) {
            const int idx = tid + t * 256;
            const int row = idx >> 2, cc = idx & 3;
            const uint32_t off = tile_off(row, cc);
            const int ar = min(m0 + row, M - 1);
            CP_ASYNC16(sb + STG_A + off, A  + (size_t)ar * K + k0 + cc * 8);
            CP_ASYNC16(sb + STG_B + off, BT + (size_t)(n0 + row) * K + k0 + cc * 8);
        }
        CP_COMMIT();
    };

    load_chunk(0, 0);
    load_chunk(1, 32);

    int stage = 0;
    for (int ch = 0; ch < nchunks; ch++) {
        if (ch + 1 < nchunks) CP_WAIT1(); else CP_WAIT0();
        __syncthreads();

        if (ch + 2 < nchunks) {
            int s2 = stage + 2; if (s2 >= NSTAGE) s2 -= NSTAGE;
            load_chunk(s2, (ch + 2) << 5);
        }

        const uint32_t sb = smem_base + stage * STG_SIZE;

        #pragma unroll
        for (int ks = 0; ks < 2; ks++) {
            const int kc = ks * 2;
            uint32_t a[4][4], b[4][2];

            #pragma unroll
            for (int fm = 0; fm < 4; fm++) {
                const int row = warp_m * 64 + fm * 16 + lrow;
                LDSM_X4(a[fm][0], a[fm][1], a[fm][2], a[fm][3],
                        sb + STG_A + tile_off(row, kc + lchk));
            }
            #pragma unroll
            for (int fp = 0; fp < 2; fp++) {
                const int row = warp_n * 32 + fp * 16 + lrow;
                uint32_t r0, r1, r2, r3;
                LDSM_X4(r0, r1, r2, r3, sb + STG_B + tile_off(row, kc + lchk));
                b[2 * fp + 0][0] = r0; b[2 * fp + 0][1] = r2;
                b[2 * fp + 1][0] = r1; b[2 * fp + 1][1] = r3;
            }
            #pragma unroll
            for (int fm = 0; fm < 4; fm++)
                #pragma unroll
                for (int fn = 0; fn < 4; fn++)
                    MMA_F16(c[fm][fn][0], c[fm][fn][1], c[fm][fn][2], c[fm][fn][3],
                            a[fm][0], a[fm][1], a[fm][2], a[fm][3],
                            b[fn][0], b[fn][1]);
        }

        stage++; if (stage >= NSTAGE) stage -= NSTAGE;
    }

    // epilogue (+bias, guarded rows)
    #pragma unroll
    for (int fm = 0; fm < 4; fm++) {
        const int r0 = m0 + warp_m * 64 + fm * 16 + (lane >> 2);
        #pragma unroll
        for (int fn = 0; fn < 4; fn++) {
            const int col = n0 + warp_n * 32 + fn * 8 + (lane & 3) * 2;
            float bx = 0.f, by = 0.f;
            if (HAS_BIAS) { bx = bias[col]; by = bias[col + 1]; }
            if (r0 < M) {
                float2 v0 = make_float2(c[fm][fn][0] + bx, c[fm][fn][1] + by);
                *reinterpret_cast<float2*>(C + (size_t)r0 * N + col) = v0;
            }
            if (r0 + 8 < M) {
                float2 v1 = make_float2(c[fm][fn][2] + bx, c[fm][fn][3] + by);
                *reinterpret_cast<float2*>(C + (size_t)(r0 + 8) * N + col) = v1;
            }
        }
    }
}

// ---------------------------------------------------------------------------
// Fused attention: 2 threads per q-row (each owns 32 of 64 dims).
// Emits fp16 for the O-projection.
// ---------------------------------------------------------------------------
__global__ __launch_bounds__(256, 2)
void attn_kernel(const float* __restrict__ Q, const float* __restrict__ Kb,
                 const float* __restrict__ Vb, const int* __restrict__ mask,
                 __half* __restrict__ Oh)
{
    __shared__ float Ks[NT_][DH_];
    __shared__ float Vs[NT_][DH_];

    const int b = blockIdx.z;
    const int h = blockIdx.y;
    const int tid = threadIdx.x;
    const int half_ = tid & 1;
    const int qr = blockIdx.x * 128 + (tid >> 1);

    for (int i = tid; i < NT_ * DH_; i += 256) {
        const int j = i >> 6;
        const int d = i & 63;
        const size_t src = ((size_t)(b * NT_ + j)) * INNER_ + h * DH_ + d;
        Ks[j][d] = Kb[src];
        Vs[j][d] = Vb[src];
    }
    __syncthreads();

    float q[32];
    const float4* qp = reinterpret_cast<const float4*>(
        Q + ((size_t)(b * NP_ + qr)) * INNER_ + h * DH_ + half_ * 32);
    #pragma unroll
    for (int i = 0; i < 8; i++) {
        float4 v = qp[i];
        q[4 * i + 0] = v.x; q[4 * i + 1] = v.y;
        q[4 * i + 2] = v.z; q[4 * i + 3] = v.w;
    }

    const int* mrow = mask + ((size_t)(b * NP_ + qr)) * NT_;

    float acc[32];
    #pragma unroll
    for (int d = 0; d < 32; d++) acc[d] = 0.f;
    float l = 0.f;

    #pragma unroll 1
    for (int j = 0; j < NT_; j++) {
        const float4* kj = reinterpret_cast<const float4*>(&Ks[j][half_ * 32]);
        float s0 = 0.f, s1 = 0.f, s2 = 0.f, s3 = 0.f;
        #pragma unroll
        for (int d4 = 0; d4 < 8; d4++) {
            float4 kv = kj[d4];
            s0 += q[4 * d4 + 0] * kv.x;
            s1 += q[4 * d4 + 1] * kv.y;
            s2 += q[4 * d4 + 2] * kv.z;
            s3 += q[4 * d4 + 3] * kv.w;
        }
        float s = (s0 + s1) + (s2 + s3);
        s += __shfl_xor_sync(0xFFFFFFFF, s, 1);
        s *= 0.125f;
        const float e = (mrow[j] != 0) ? __expf(s) : 0.f;
        l += e;
        const float4* vj = reinterpret_cast<const float4*>(&Vs[j][half_ * 32]);
        #pragma unroll
        for (int d4 = 0; d4 < 8; d4++) {
            float4 vv = vj[d4];
            acc[4 * d4 + 0] += e * vv.x;
            acc[4 * d4 + 1] += e * vv.y;
            acc[4 * d4 + 2] += e * vv.z;
            acc[4 * d4 + 3] += e * vv.w;
        }
    }

    const float inv = 1.f / l;
    const size_t obase = ((size_t)(b * NP_ + qr)) * INNER_ + h * DH_ + half_ * 32;
    __half2* ph = reinterpret_cast<__half2*>(Oh + obase);
    #pragma unroll
    for (int d = 0; d < 32; d += 2)
        ph[d >> 1] = __floats2half2_rn(acc[d] * inv, acc[d + 1] * inv);
}

// ---------------------------------------------------------------------------
// Launch
// ---------------------------------------------------------------------------
extern "C" void kernel_launch(void* const* d_in, const int* in_sizes, int n_in,
                              void* d_out, int out_size)
{
    const float* x    = (const float*)d_in[0];
    const float* ctx  = (const float*)d_in[1];
    const int*   mask = (const int*)  d_in[2];
    const float* Wq   = (const float*)d_in[3];
    const float* Wk   = (const float*)d_in[4];
    const float* Wv   = (const float*)d_in[5];
    const float* Wo   = (const float*)d_in[6];
    const float* bo   = (const float*)d_in[7];
    float* out = (float*)d_out;

    float *Qb, *Kb, *Vb;
    __half *xh, *ah, *ch, *wt, *wkt, *wvt;
    cudaGetSymbolAddress((void**)&Qb,  g_Q);
    cudaGetSymbolAddress((void**)&Kb,  g_Kp);
    cudaGetSymbolAddress((void**)&Vb,  g_Vp);
    cudaGetSymbolAddress((void**)&xh,  g_xh);
    cudaGetSymbolAddress((void**)&ah,  g_ah);
    cudaGetSymbolAddress((void**)&ch,  g_ch);
    cudaGetSymbolAddress((void**)&wt,  g_Wt);
    cudaGetSymbolAddress((void**)&wkt, g_WkT);
    cudaGetSymbolAddress((void**)&wvt, g_WvT);

    cudaFuncSetAttribute(mma_gemm_pipe<false>,
                         cudaFuncAttributeMaxDynamicSharedMemorySize, PIPE_SMEM);
    cudaFuncSetAttribute(mma_gemm_pipe<true>,
                         cudaFuncAttributeMaxDynamicSharedMemorySize, PIPE_SMEM);

    const int Mq = B_ * NP_;   // 65536
    const int Mc = B_ * NT_;   // 1232

    // conversions
    {
        const int n4 = Mq * QD_ / 4;
        tohalf_kernel<<<(n4 + 255) / 256, 256>>>((const float4*)x, (__half2*)xh, n4);
    }
    {
        const int n4 = Mc * CD_ / 4;
        tohalf_kernel<<<(n4 + 255) / 256, 256>>>((const float4*)ctx, (__half2*)ch, n4);
    }
    transT_kernel<<<(QD_ * INNER_ + 255) / 256, 256>>>(Wq, wt, QD_, INNER_);
    transT_kernel<<<(CD_ * INNER_ + 255) / 256, 256>>>(Wk, wkt, CD_, INNER_);
    transT_kernel<<<(CD_ * INNER_ + 255) / 256, 256>>>(Wv, wvt, CD_, INNER_);

    // Q = x @ Wq
    mma_gemm_pipe<false><<<dim3(INNER_ / 128, Mq / 128, 1), 256, PIPE_SMEM>>>(
        xh, wt, Qb, wt, Qb, nullptr, Mq, INNER_, QD_);

    // K = ctx @ Wk, V = ctx @ Wv (fused via gridDim.z)
    mma_gemm_pipe<false><<<dim3(INNER_ / 128, (Mc + 127) / 128, 2), 256, PIPE_SMEM>>>(
        ch, wkt, Kb, wvt, Vb, nullptr, Mc, INNER_, CD_);

    // fused attention -> fp16
    attn_kernel<<<dim3(NP_ / 128, H_, B_), 256>>>(Qb, Kb, Vb, mask, ah);

    // Wo^T (stream-ordered reuse of wt)
    transT_kernel<<<(INNER_ * QD_ + 255) / 256, 256>>>(Wo, wt, INNER_, QD_);

    // out = Att @ Wo + bo
    mma_gemm_pipe<true><<<dim3(QD_ / 128, Mq / 128, 1), 256, PIPE_SMEM>>>(
        ah, wt, out, wt, out, bo, Mq, QD_, INNER_);
}

// round 6
// speedup vs baseline: 5.5911x; 2.1883x over previous
#include <cuda_runtime.h>
#include <cuda_fp16.h>
#include <cstdint>

// Problem constants
#define B_   16
#define NP_  4096
#define NT_  77
#define QD_  512
#define CD_  768
#define H_   8
#define DH_  64
#define INNER_ 512   // H*DH

// ---------------------------------------------------------------------------
// Scratch (device globals)
// ---------------------------------------------------------------------------
__device__ __half g_Qh [(size_t)B_ * NP_ * INNER_];
__device__ __half g_Kh [(size_t)B_ * NT_ * INNER_];
__device__ __half g_Vh [(size_t)B_ * NT_ * INNER_];
__device__ __half g_xh [(size_t)B_ * NP_ * QD_];
__device__ __half g_ah [(size_t)B_ * NP_ * INNER_];
__device__ __half g_ch [(size_t)B_ * NT_ * CD_];
__device__ __half g_Wt [(size_t)QD_ * INNER_];    // Wq^T / Wo^T  [N,K]
__device__ __half g_WkT[(size_t)CD_ * INNER_];
__device__ __half g_WvT[(size_t)CD_ * INNER_];

// ---------------------------------------------------------------------------
// PTX helpers (base sm_103-safe: ldmatrix / mma.sync / cp.async)
// ---------------------------------------------------------------------------
__device__ __forceinline__ uint32_t smem_u32(const void* p) {
    uint32_t a;
    asm("{ .reg .u64 t; cvta.to.shared.u64 t, %1; cvt.u32.u64 %0, t; }" : "=r"(a) : "l"(p));
    return a;
}

#define LDSM_X4(r0, r1, r2, r3, addr) \
    asm volatile("ldmatrix.sync.aligned.m8n8.x4.shared.b16 {%0,%1,%2,%3}, [%4];" \
        : "=r"(r0), "=r"(r1), "=r"(r2), "=r"(r3) : "r"(addr))

#define MMA_F16(c0, c1, c2, c3, a0, a1, a2, a3, b0, b1) \
    asm volatile("mma.sync.aligned.m16n8k16.row.col.f32.f16.f16.f32 " \
        "{%0,%1,%2,%3}, {%4,%5,%6,%7}, {%8,%9}, {%0,%1,%2,%3};" \
        : "+f"(c0), "+f"(c1), "+f"(c2), "+f"(c3) \
        : "r"(a0), "r"(a1), "r"(a2), "r"(a3), "r"(b0), "r"(b1))

#define CP_ASYNC16(dst, src) \
    asm volatile("cp.async.cg.shared.global [%0], [%1], 16;" :: "r"(dst), "l"(src))
#define CP_COMMIT() asm volatile("cp.async.commit_group;" ::: "memory")
#define CP_WAIT1()  asm volatile("cp.async.wait_group 1;" ::: "memory")
#define CP_WAIT0()  asm volatile("cp.async.wait_group 0;" ::: "memory")

// GEMM smem tile: 128 rows x 32 fp16 (64B/row); 16B chunks XOR-swizzled.
__device__ __forceinline__ uint32_t tile_off(int row, int chunk) {
    return (uint32_t)(row * 64 + ((chunk ^ ((row >> 1) & 3)) << 4));
}

__device__ __forceinline__ uint32_t packh2(float x, float y) {
    __half2 h = __floats2half2_rn(x, y);
    return *reinterpret_cast<uint32_t*>(&h);
}

// ---------------------------------------------------------------------------
// fp32 -> fp16 conversion
// ---------------------------------------------------------------------------
__global__ __launch_bounds__(256)
void tohalf_kernel(const float4* __restrict__ in, __half2* __restrict__ out, int n4)
{
    int i = blockIdx.x * 256 + threadIdx.x;
    if (i >= n4) return;
    float4 v = in[i];
    out[2 * i]     = __floats2half2_rn(v.x, v.y);
    out[2 * i + 1] = __floats2half2_rn(v.z, v.w);
}

// transpose + convert weight: in [K,N] fp32 -> out [N,K] fp16
__global__ __launch_bounds__(256)
void transT_kernel(const float* __restrict__ in, __half* __restrict__ outT, int K, int N)
{
    int i = blockIdx.x * 256 + threadIdx.x;
    if (i >= N * K) return;
    int n = i / K, k = i % K;
    outT[i] = __float2half_rn(in[(size_t)k * N + n]);
}

// ---------------------------------------------------------------------------
// Pipelined fp16 mma.sync GEMM: C[M,N] = A[M,K] @ BT[N,K]^T
// fp32 accum; output fp32 (+bias) or fp16 via OUT_HALF.
// 128x128 CTA tile, BK=32, 3-stage cp.async pipeline, 8 warps of 64x32.
// gridDim.z selects B/C set (fused K+V projection).
// ---------------------------------------------------------------------------
#define STG_A 0
#define STG_B 8192
#define STG_SIZE 16384
#define NSTAGE 3
#define PIPE_SMEM (NSTAGE * STG_SIZE)

template<bool HAS_BIAS, bool OUT_HALF>
__global__ __launch_bounds__(256, 2)
void mma_gemm_pipe(const __half* __restrict__ A,
                   const __half* __restrict__ B0, void* __restrict__ C0,
                   const __half* __restrict__ B1, void* __restrict__ C1,
                   const float* __restrict__ bias, int M, int N, int K)
{
    extern __shared__ __align__(1024) char dsm[];
    const uint32_t smem_base = smem_u32(dsm);

    const __half* BT = blockIdx.z ? B1 : B0;
    void*         Cv = blockIdx.z ? C1 : C0;

    const int tid  = threadIdx.x;
    const int wid  = tid >> 5;
    const int lane = tid & 31;
    const int warp_m = wid >> 2;
    const int warp_n = wid & 3;
    const int m0 = blockIdx.y * 128;
    const int n0 = blockIdx.x * 128;

    float c[4][4][4];
    #pragma unroll
    for (int i = 0; i < 4; i++)
        #pragma unroll
        for (int j = 0; j < 4; j++)
            #pragma unroll
            for (int r = 0; r < 4; r++) c[i][j][r] = 0.f;

    const int lrow = lane & 15;
    const int lchk = lane >> 4;
    const int nchunks = K >> 5;

    auto load_chunk = [&](int s, int k0) {
        const uint32_t sb = smem_base + s * STG_SIZE;
        #pragma unroll
        for (int t = 0; t < 2; t++) {
            const int idx = tid + t * 256;
            const int row = idx >> 2, cc = idx & 3;
            const uint32_t off = tile_off(row, cc);
            const int ar = min(m0 + row, M - 1);
            CP_ASYNC16(sb + STG_A + off, A  + (size_t)ar * K + k0 + cc * 8);
            CP_ASYNC16(sb + STG_B + off, BT + (size_t)(n0 + row) * K + k0 + cc * 8);
        }
        CP_COMMIT();
    };

    load_chunk(0, 0);
    load_chunk(1, 32);

    int stage = 0;
    for (int ch = 0; ch < nchunks; ch++) {
        if (ch + 1 < nchunks) CP_WAIT1(); else CP_WAIT0();
        __syncthreads();

        if (ch + 2 < nchunks) {
            int s2 = stage + 2; if (s2 >= NSTAGE) s2 -= NSTAGE;
            load_chunk(s2, (ch + 2) << 5);
        }

        const uint32_t sb = smem_base + stage * STG_SIZE;

        #pragma unroll
        for (int ks = 0; ks < 2; ks++) {
            const int kc = ks * 2;
            uint32_t a[4][4], b[4][2];

            #pragma unroll
            for (int fm = 0; fm < 4; fm++) {
                const int row = warp_m * 64 + fm * 16 + lrow;
                LDSM_X4(a[fm][0], a[fm][1], a[fm][2], a[fm][3],
                        sb + STG_A + tile_off(row, kc + lchk));
            }
            #pragma unroll
            for (int fp = 0; fp < 2; fp++) {
                const int row = warp_n * 32 + fp * 16 + lrow;
                uint32_t r0, r1, r2, r3;
                LDSM_X4(r0, r1, r2, r3, sb + STG_B + tile_off(row, kc + lchk));
                b[2 * fp + 0][0] = r0; b[2 * fp + 0][1] = r2;
                b[2 * fp + 1][0] = r1; b[2 * fp + 1][1] = r3;
            }
            #pragma unroll
            for (int fm = 0; fm < 4; fm++)
                #pragma unroll
                for (int fn = 0; fn < 4; fn++)
                    MMA_F16(c[fm][fn][0], c[fm][fn][1], c[fm][fn][2], c[fm][fn][3],
                            a[fm][0], a[fm][1], a[fm][2], a[fm][3],
                            b[fn][0], b[fn][1]);
        }

        stage++; if (stage >= NSTAGE) stage -= NSTAGE;
    }

    // epilogue
    #pragma unroll
    for (int fm = 0; fm < 4; fm++) {
        const int r0 = m0 + warp_m * 64 + fm * 16 + (lane >> 2);
        #pragma unroll
        for (int fn = 0; fn < 4; fn++) {
            const int col = n0 + warp_n * 32 + fn * 8 + (lane & 3) * 2;
            if (OUT_HALF) {
                __half* C = (__half*)Cv;
                if (r0 < M)
                    *reinterpret_cast<__half2*>(C + (size_t)r0 * N + col) =
                        __floats2half2_rn(c[fm][fn][0], c[fm][fn][1]);
                if (r0 + 8 < M)
                    *reinterpret_cast<__half2*>(C + (size_t)(r0 + 8) * N + col) =
                        __floats2half2_rn(c[fm][fn][2], c[fm][fn][3]);
            } else {
                float* C = (float*)Cv;
                float bx = 0.f, by = 0.f;
                if (HAS_BIAS) { bx = bias[col]; by = bias[col + 1]; }
                if (r0 < M)
                    *reinterpret_cast<float2*>(C + (size_t)r0 * N + col) =
                        make_float2(c[fm][fn][0] + bx, c[fm][fn][1] + by);
                if (r0 + 8 < M)
                    *reinterpret_cast<float2*>(C + (size_t)(r0 + 8) * N + col) =
                        make_float2(c[fm][fn][2] + bx, c[fm][fn][3] + by);
            }
        }
    }
}

// ---------------------------------------------------------------------------
// Tensor-core flash attention.
// CTA: 128 q rows x one (b,h). 8 warps, warp w owns rows 16w..16w+15.
// S = Q@K^T (mma), softmax in C-frag layout, P frags repacked as A frags,
// O = P@V^T (mma, V transposed in smem), normalized at store.
// ---------------------------------------------------------------------------
#define NTP 80                 // NT padded to mma n-multiple
#define QS_PITCH 72            // 64 + 8 halves -> conflict-free ldmatrix
#define VT_PITCH 88            // 80 + 8 halves

__global__ __launch_bounds__(256)
void fattn_kernel(const __half* __restrict__ Qh, const __half* __restrict__ Kh,
                  const __half* __restrict__ Vh, const int* __restrict__ mask,
                  __half* __restrict__ Oh)
{
    __shared__ __half Qs[128 * QS_PITCH];
    __shared__ __half Ks[NTP * QS_PITCH];
    __shared__ __half Vt[DH_ * VT_PITCH];

    const int b = blockIdx.z;
    const int h = blockIdx.y;
    const int q0 = blockIdx.x * 128;
    const int tid = threadIdx.x;
    const int wid = tid >> 5;
    const int lane = tid & 31;

    const uint32_t qs = smem_u32(Qs);
    const uint32_t ks = smem_u32(Ks);
    const uint32_t vt = smem_u32(Vt);

    // --- async load Q tile: 128 rows x 64 halves (8x16B chunks per row) ---
    #pragma unroll
    for (int t = 0; t < 4; t++) {
        const int idx = tid + t * 256;          // 0..1023
        const int row = idx >> 3, cc = idx & 7;
        CP_ASYNC16(qs + (row * QS_PITCH + cc * 8) * 2,
                   Qh + ((size_t)(b * NP_ + q0 + row)) * INNER_ + h * DH_ + cc * 8);
    }
    // --- async load K tile: 77 rows x 64 halves ---
    for (int idx = tid; idx < NT_ * 8; idx += 256) {
        const int row = idx >> 3, cc = idx & 7;
        CP_ASYNC16(ks + (row * QS_PITCH + cc * 8) * 2,
                   Kh + ((size_t)(b * NT_ + row)) * INNER_ + h * DH_ + cc * 8);
    }
    CP_COMMIT();

    // zero K pad rows (77..79) and Vt (full, covers t-pad)
    for (int i = tid; i < 3 * QS_PITCH; i += 256)
        Ks[NT_ * QS_PITCH + i] = __float2half(0.f);
    for (int i = tid; i < DH_ * VT_PITCH / 2; i += 256)
        reinterpret_cast<__half2*>(Vt)[i] = __half2(__float2half(0.f), __float2half(0.f));
    __syncthreads();   // Vt zero visible before transpose fill

    // --- V transpose fill: Vt[d][t] = V[t][d] ---
    for (int idx = tid; idx < NT_ * DH_; idx += 256) {
        const int t = idx >> 6, d = idx & 63;
        Vt[d * VT_PITCH + t] = Vh[((size_t)(b * NT_ + t)) * INNER_ + h * DH_ + d];
    }
    CP_WAIT0();
    __syncthreads();

    const int lrow = lane & 15;
    const int lchk = lane >> 4;

    // --- S = Q @ K^T : warp rows 16*wid, cols 0..79 (10 n8 frags) ---
    float s[10][4];
    #pragma unroll
    for (int f = 0; f < 10; f++)
        #pragma unroll
        for (int r = 0; r < 4; r++) s[f][r] = 0.f;

    #pragma unroll
    for (int kstep = 0; kstep < 4; kstep++) {
        const int kc = kstep * 2;
        uint32_t a0, a1, a2, a3;
        LDSM_X4(a0, a1, a2, a3,
                qs + ((wid * 16 + lrow) * QS_PITCH + (kc + lchk) * 8) * 2);
        #pragma unroll
        for (int g = 0; g < 5; g++) {
            uint32_t r0, r1, r2, r3;
            LDSM_X4(r0, r1, r2, r3,
                    ks + ((g * 16 + lrow) * QS_PITCH + (kc + lchk) * 8) * 2);
            MMA_F16(s[2*g+0][0], s[2*g+0][1], s[2*g+0][2], s[2*g+0][3],
                    a0, a1, a2, a3, r0, r2);
            MMA_F16(s[2*g+1][0], s[2*g+1][1], s[2*g+1][2], s[2*g+1][3],
                    a0, a1, a2, a3, r1, r3);
        }
    }

    // --- softmax (no-max exp; scores O(1)), mask, row sums ---
    const int ra = q0 + wid * 16 + (lane >> 2);   // row for c0,c1
    const int rb = ra + 8;                        // row for c2,c3
    const int* ma = mask + ((size_t)(b * NP_ + ra)) * NT_;
    const int* mb = mask + ((size_t)(b * NP_ + rb)) * NT_;

    float suma = 0.f, sumb = 0.f;
    #pragma unroll
    for (int f = 0; f < 10; f++) {
        const int t0 = f * 8 + (lane & 3) * 2;
        const int t1 = t0 + 1;
        float e0 = (t0 < NT_ && ma[t0] != 0) ? __expf(s[f][0] * 0.125f) : 0.f;
        float e1 = (t1 < NT_ && ma[t1] != 0) ? __expf(s[f][1] * 0.125f) : 0.f;
        float e2 = (t0 < NT_ && mb[t0] != 0) ? __expf(s[f][2] * 0.125f) : 0.f;
        float e3 = (t1 < NT_ && mb[t1] != 0) ? __expf(s[f][3] * 0.125f) : 0.f;
        s[f][0] = e0; s[f][1] = e1; s[f][2] = e2; s[f][3] = e3;
        suma += e0 + e1;
        sumb += e2 + e3;
    }
    suma += __shfl_xor_sync(0xFFFFFFFF, suma, 1);
    suma += __shfl_xor_sync(0xFFFFFFFF, suma, 2);
    sumb += __shfl_xor_sync(0xFFFFFFFF, sumb, 1);
    sumb += __shfl_xor_sync(0xFFFFFFFF, sumb, 2);
    const float inva = 1.f / suma;
    const float invb = 1.f / sumb;

    // --- repack P (C-frags) into A-frags for P@V ---
    uint32_t p[5][4];
    #pragma unroll
    for (int kstep = 0; kstep < 5; kstep++) {
        const int f0 = 2 * kstep, f1 = 2 * kstep + 1;
        p[kstep][0] = packh2(s[f0][0], s[f0][1]);
        p[kstep][1] = packh2(s[f0][2], s[f0][3]);
        p[kstep][2] = packh2(s[f1][0], s[f1][1]);
        p[kstep][3] = packh2(s[f1][2], s[f1][3]);
    }

    // --- O = P @ Vt^T : 8 n8 frags over d=64 ---
    float o[8][4];
    #pragma unroll
    for (int f = 0; f < 8; f++)
        #pragma unroll
        for (int r = 0; r < 4; r++) o[f][r] = 0.f;

    #pragma unroll
    for (int kstep = 0; kstep < 5; kstep++) {
        const int tc = kstep * 2;
        #pragma unroll
        for (int g = 0; g < 4; g++) {
            uint32_t r0, r1, r2, r3;
            LDSM_X4(r0, r1, r2, r3,
                    vt + ((g * 16 + lrow) * VT_PITCH + (tc + lchk) * 8) * 2);
            MMA_F16(o[2*g+0][0], o[2*g+0][1], o[2*g+0][2], o[2*g+0][3],
                    p[kstep][0], p[kstep][1], p[kstep][2], p[kstep][3], r0, r2);
            MMA_F16(o[2*g+1][0], o[2*g+1][1], o[2*g+1][2], o[2*g+1][3],
                    p[kstep][0], p[kstep][1], p[kstep][2], p[kstep][3], r1, r3);
        }
    }

    // --- normalize + store fp16 ---
    __half* outA = Oh + ((size_t)(b * NP_ + ra)) * INNER_ + h * DH_;
    __half* outB = Oh + ((size_t)(b * NP_ + rb)) * INNER_ + h * DH_;
    #pragma unroll
    for (int f = 0; f < 8; f++) {
        const int d = f * 8 + (lane & 3) * 2;
        *reinterpret_cast<__half2*>(outA + d) =
            __floats2half2_rn(o[f][0] * inva, o[f][1] * inva);
        *reinterpret_cast<__half2*>(outB + d) =
            __floats2half2_rn(o[f][2] * invb, o[f][3] * invb);
    }
}

// ---------------------------------------------------------------------------
// Launch
// ---------------------------------------------------------------------------
extern "C" void kernel_launch(void* const* d_in, const int* in_sizes, int n_in,
                              void* d_out, int out_size)
{
    const float* x    = (const float*)d_in[0];
    const float* ctx  = (const float*)d_in[1];
    const int*   mask = (const int*)  d_in[2];
    const float* Wq   = (const float*)d_in[3];
    const float* Wk   = (const float*)d_in[4];
    const float* Wv   = (const float*)d_in[5];
    const float* Wo   = (const float*)d_in[6];
    const float* bo   = (const float*)d_in[7];
    float* out = (float*)d_out;

    __half *Qh, *Kh, *Vh, *xh, *ah, *ch, *wt, *wkt, *wvt;
    cudaGetSymbolAddress((void**)&Qh,  g_Qh);
    cudaGetSymbolAddress((void**)&Kh,  g_Kh);
    cudaGetSymbolAddress((void**)&Vh,  g_Vh);
    cudaGetSymbolAddress((void**)&xh,  g_xh);
    cudaGetSymbolAddress((void**)&ah,  g_ah);
    cudaGetSymbolAddress((void**)&ch,  g_ch);
    cudaGetSymbolAddress((void**)&wt,  g_Wt);
    cudaGetSymbolAddress((void**)&wkt, g_WkT);
    cudaGetSymbolAddress((void**)&wvt, g_WvT);

    cudaFuncSetAttribute((const void*)mma_gemm_pipe<false, true>,
                         cudaFuncAttributeMaxDynamicSharedMemorySize, PIPE_SMEM);
    cudaFuncSetAttribute((const void*)mma_gemm_pipe<true, false>,
                         cudaFuncAttributeMaxDynamicSharedMemorySize, PIPE_SMEM);

    const int Mq = B_ * NP_;   // 65536
    const int Mc = B_ * NT_;   // 1232

    // conversions
    {
        const int n4 = Mq * QD_ / 4;
        tohalf_kernel<<<(n4 + 255) / 256, 256>>>((const float4*)x, (__half2*)xh, n4);
    }
    {
        const int n4 = Mc * CD_ / 4;
        tohalf_kernel<<<(n4 + 255) / 256, 256>>>((const float4*)ctx, (__half2*)ch, n4);
    }
    transT_kernel<<<(QD_ * INNER_ + 255) / 256, 256>>>(Wq, wt, QD_, INNER_);
    transT_kernel<<<(CD_ * INNER_ + 255) / 256, 256>>>(Wk, wkt, CD_, INNER_);
    transT_kernel<<<(CD_ * INNER_ + 255) / 256, 256>>>(Wv, wvt, CD_, INNER_);

    // Q = x @ Wq  (fp16 out)
    mma_gemm_pipe<false, true><<<dim3(INNER_ / 128, Mq / 128, 1), 256, PIPE_SMEM>>>(
        xh, wt, Qh, wt, Qh, nullptr, Mq, INNER_, QD_);

    // K, V = ctx @ {Wk, Wv}  (fp16 out, fused via gridDim.z)
    mma_gemm_pipe<false, true><<<dim3(INNER_ / 128, (Mc + 127) / 128, 2), 256, PIPE_SMEM>>>(
        ch, wkt, Kh, wvt, Vh, nullptr, Mc, INNER_, CD_);

    // tensor-core flash attention -> fp16
    fattn_kernel<<<dim3(NP_ / 128, H_, B_), 256>>>(Qh, Kh, Vh, mask, ah);

    // Wo^T (stream-ordered reuse of wt)
    transT_kernel<<<(INNER_ * QD_ + 255) / 256, 256>>>(Wo, wt, INNER_, QD_);

    // out = Att @ Wo + bo  (fp32 out + bias)
    mma_gemm_pipe<true, false><<<dim3(QD_ / 128, Mq / 128, 1), 256, PIPE_SMEM>>>(
        ah, wt, out, wt, out, bo, Mq, QD_, INNER_);
}